// round 10
// baseline (speedup 1.0000x reference)
#include <cuda_runtime.h>
#include <cuda_fp16.h>
#include <cstdint>

#define N_NODES 50000
#define N_EDGES 800000
#define D 128
#define UPAD 132   // padded smem row stride (floats)

// ---------------------------------------------------------------------------
// Device scratch
// ---------------------------------------------------------------------------
__device__ int     g_cin[N_NODES];        // deg_in  - 1 (src counts)
__device__ int     g_cnt[N_NODES];        // deg_out - 1 (dst counts)
__device__ int     g_rowptr[N_NODES + 1];
__device__ int     g_cursor[N_NODES];
__device__ int     g_col[N_EDGES];
__device__ float   g_sout[N_NODES];       // rsqrt(deg_out)
__device__ __half  g_xsh[N_NODES * D];    // fp16( x * rsqrt(deg_in) )
__device__ float2  g_W2[D * (D / 2)];     // W2[k*64+j] = {W[2j][k], W[2j+1][k]}
__device__ int     g_bsum[256];           // per-block count sums (196 used)

// ---------------------------------------------------------------------------
// Packed f32x2 helpers
// ---------------------------------------------------------------------------
__device__ __forceinline__ unsigned long long pack2dup(float v) {
    unsigned long long r;
    asm("mov.b64 %0, {%1, %1};" : "=l"(r) : "f"(v));
    return r;
}
__device__ __forceinline__ void fma2(unsigned long long& d,
                                     unsigned long long a,
                                     unsigned long long b) {
    asm("fma.rn.f32x2 %0, %1, %2, %0;" : "+l"(d) : "l"(a), "l"(b));
}
__device__ __forceinline__ void unpack2(unsigned long long v, float& lo, float& hi) {
    asm("mov.b64 {%0, %1}, %2;" : "=f"(lo), "=f"(hi) : "l"(v));
}

#define ZB ((N_NODES + 255) / 256)        // 196
#define DB ((N_EDGES + 255) / 256)        // 3125
#define WB ((D * (D / 2) + 255) / 256)    // 32
#define SB ((N_NODES * (D / 4) + 255) / 256)  // 6250

// ---------------------------------------------------------------------------
// Kernel 1: zero degree counters
// ---------------------------------------------------------------------------
__global__ void zero_kernel() {
    int i = blockIdx.x * blockDim.x + threadIdx.x;
    if (i < N_NODES) { g_cin[i] = 0; g_cnt[i] = 0; }
}

// ---------------------------------------------------------------------------
// Kernel 2: degree counts + W pack (disjoint block ranges)
// ---------------------------------------------------------------------------
__global__ __launch_bounds__(256) void prep2_kernel(const int2* __restrict__ edges,
                                                    const float* __restrict__ Wm) {
    int bid = blockIdx.x;
    if (bid < DB) {
        int i = bid * 256 + threadIdx.x;
        if (i < N_EDGES) {
            int2 e = edges[i];
            atomicAdd(&g_cin[e.x], 1);
            atomicAdd(&g_cnt[e.y], 1);
        }
    } else {
        int i = (bid - DB) * 256 + threadIdx.x;
        if (i < D * (D / 2)) {
            int k = i >> 6;
            int j = i & 63;
            g_W2[i] = make_float2(Wm[(2 * j) * D + k], Wm[(2 * j + 1) * D + k]);
        }
    }
}

// ---------------------------------------------------------------------------
// Kernel 3: scale + scanA (disjoint block ranges)
// ---------------------------------------------------------------------------
__global__ __launch_bounds__(256) void scale_scanA_kernel(const float* __restrict__ x) {
    int bid = blockIdx.x;
    if (bid < SB) {
        int i = bid * 256 + threadIdx.x;         // float4 index
        if (i < N_NODES * (D / 4)) {
            int row = i >> 5;
            float s = rsqrtf((float)(g_cin[row] + 1));
            float4 v = reinterpret_cast<const float4*>(x)[i];
            __half2 h0 = __floats2half2_rn(v.x * s, v.y * s);
            __half2 h1 = __floats2half2_rn(v.z * s, v.w * s);
            *reinterpret_cast<__half2*>(&g_xsh[(size_t)i * 4])     = h0;
            *reinterpret_cast<__half2*>(&g_xsh[(size_t)i * 4 + 2]) = h1;
            if ((i & 31) == 0) g_sout[row] = rsqrtf((float)(g_cnt[row] + 1));
        }
    } else {
        __shared__ int sh[8];
        int blk = bid - SB;
        int i = blk * 256 + threadIdx.x;
        int v = (i < N_NODES) ? g_cnt[i] : 0;
        int lane = threadIdx.x & 31, warp = threadIdx.x >> 5;
#pragma unroll
        for (int o = 16; o > 0; o >>= 1) v += __shfl_down_sync(0xffffffffu, v, o);
        if (lane == 0) sh[warp] = v;
        __syncthreads();
        if (warp == 0) {
            int w = (lane < 8) ? sh[lane] : 0;
#pragma unroll
            for (int o = 4; o > 0; o >>= 1) w += __shfl_down_sync(0xffffffffu, w, o);
            if (lane == 0) g_bsum[blk] = w;
        }
    }
}

// ---------------------------------------------------------------------------
// Kernel 4: fused scanB+scanC
// ---------------------------------------------------------------------------
__global__ __launch_bounds__(256) void scanBC_kernel() {
    __shared__ int bs[256];
    __shared__ int sh[256];
    int t = threadIdx.x;

    int bv = (t < ZB) ? g_bsum[t] : 0;
    bs[t] = bv;
    __syncthreads();
    for (int off = 1; off < 256; off <<= 1) {
        int a = (t >= off) ? bs[t - off] : 0;
        __syncthreads();
        bs[t] += a;
        __syncthreads();
    }
    int boff  = (blockIdx.x > 0) ? bs[blockIdx.x - 1] : 0;
    int total = bs[ZB - 1];

    int i = blockIdx.x * 256 + t;
    int v = (i < N_NODES) ? g_cnt[i] : 0;
    sh[t] = v;
    __syncthreads();
    for (int off = 1; off < 256; off <<= 1) {
        int a = (t >= off) ? sh[t - off] : 0;
        __syncthreads();
        sh[t] += a;
        __syncthreads();
    }
    if (i < N_NODES) {
        int p = boff + sh[t] - v;
        g_rowptr[i] = p;
        g_cursor[i] = p;
    }
    if (blockIdx.x == 0 && t == 0) g_rowptr[N_NODES] = total;
}

// ---------------------------------------------------------------------------
// Kernel 5: fill CSR column array
// ---------------------------------------------------------------------------
__global__ void fill_kernel(const int2* __restrict__ edges) {
    int i = blockIdx.x * blockDim.x + threadIdx.x;
    if (i < N_EDGES) {
        int2 e = edges[i];
        int pos = atomicAdd(&g_cursor[e.y], 1);
        g_col[pos] = e.x;
    }
}

// ---------------------------------------------------------------------------
// Kernel 6: FUSED gather + GEMM.
//   Phase 1 (warp w): gather rows [8w, 8w+8) into padded smem U tile.
//   Phase 2: out = relu(U @ W^T + b). Warp w owns col-pairs [8w, 8w+8);
//     thread (w,l) computes rows {l, l+32} x 16 cols. W loaded via
//     warp-uniform __ldg(ulonglong2) -> aligned 64-bit pairs, no pack MOVs.
//   Phase 3: epilogue transpose through smem for coalesced stores.
// ---------------------------------------------------------------------------
#define GEMM_ROWS 64
__global__ __launch_bounds__(256, 3) void fused_kernel(
    const float* __restrict__ b, float* __restrict__ out) {
    __shared__ float Us[GEMM_ROWS * UPAD];   // 33.8KB

    int tid  = threadIdx.x;
    int lane = tid & 31;
    int warp = tid >> 5;
    int row0 = blockIdx.x * GEMM_ROWS;
    int r0   = warp * 8;

    // ---- Phase 1: gather rows [8w, 8w+8) ----
    {
        const __half2* xs2 = reinterpret_cast<const __half2*>(g_xsh);
        int fo = lane * 2;                     // half2 index within row [0,64)
#pragma unroll 2
        for (int i = 0; i < 8; i++) {
            int node = row0 + r0 + i;
            float2 a0 = make_float2(0.f, 0.f);
            float2 a1 = make_float2(0.f, 0.f);
            if (node < N_NODES) {
                uint2 raw = *reinterpret_cast<const uint2*>(&xs2[(size_t)node * 64 + fo]);
                a0 = __half22float2(*reinterpret_cast<__half2*>(&raw.x));
                a1 = __half22float2(*reinterpret_cast<__half2*>(&raw.y));
                int s = g_rowptr[node];
                int e = g_rowptr[node + 1];
                int j = s;
                for (; j + 4 <= e; j += 4) {
                    int u0 = g_col[j + 0];
                    int u1 = g_col[j + 1];
                    int u2 = g_col[j + 2];
                    int u3 = g_col[j + 3];
                    uint2 q0 = *reinterpret_cast<const uint2*>(&xs2[(size_t)u0 * 64 + fo]);
                    uint2 q1 = *reinterpret_cast<const uint2*>(&xs2[(size_t)u1 * 64 + fo]);
                    uint2 q2 = *reinterpret_cast<const uint2*>(&xs2[(size_t)u2 * 64 + fo]);
                    uint2 q3 = *reinterpret_cast<const uint2*>(&xs2[(size_t)u3 * 64 + fo]);
                    float2 f;
                    f = __half22float2(*reinterpret_cast<__half2*>(&q0.x)); a0.x += f.x; a0.y += f.y;
                    f = __half22float2(*reinterpret_cast<__half2*>(&q0.y)); a1.x += f.x; a1.y += f.y;
                    f = __half22float2(*reinterpret_cast<__half2*>(&q1.x)); a0.x += f.x; a0.y += f.y;
                    f = __half22float2(*reinterpret_cast<__half2*>(&q1.y)); a1.x += f.x; a1.y += f.y;
                    f = __half22float2(*reinterpret_cast<__half2*>(&q2.x)); a0.x += f.x; a0.y += f.y;
                    f = __half22float2(*reinterpret_cast<__half2*>(&q2.y)); a1.x += f.x; a1.y += f.y;
                    f = __half22float2(*reinterpret_cast<__half2*>(&q3.x)); a0.x += f.x; a0.y += f.y;
                    f = __half22float2(*reinterpret_cast<__half2*>(&q3.y)); a1.x += f.x; a1.y += f.y;
                }
                for (; j < e; j++) {
                    int u = g_col[j];
                    uint2 q = *reinterpret_cast<const uint2*>(&xs2[(size_t)u * 64 + fo]);
                    float2 f;
                    f = __half22float2(*reinterpret_cast<__half2*>(&q.x)); a0.x += f.x; a0.y += f.y;
                    f = __half22float2(*reinterpret_cast<__half2*>(&q.y)); a1.x += f.x; a1.y += f.y;
                }
                float so = g_sout[node];
                a0.x *= so; a0.y *= so; a1.x *= so; a1.y *= so;
            }
            *reinterpret_cast<float4*>(&Us[(r0 + i) * UPAD + lane * 4]) =
                make_float4(a0.x, a0.y, a1.x, a1.y);
        }
    }
    __syncthreads();

    // ---- Phase 2: GEMM ----
    // acc[r][p]: r in {0: row=lane, 1: row=lane+32}, p = col-pair 8w+p
    unsigned long long acc[2][8];
#pragma unroll
    for (int r = 0; r < 2; r++)
#pragma unroll
        for (int p = 0; p < 8; p++) acc[r][p] = 0ull;

    const ulonglong2* W16 = reinterpret_cast<const ulonglong2*>(g_W2);
    // ulonglong2 index for (k, pair jp): k*32 + jp/2 ; jp = 8*warp + 2m
    int wbase = warp * 4;

#pragma unroll 4
    for (int k = 0; k < D; k += 4) {
        float4 ua = *reinterpret_cast<const float4*>(&Us[lane * UPAD + k]);
        float4 ub = *reinterpret_cast<const float4*>(&Us[(lane + 32) * UPAD + k]);
        float uav[4] = {ua.x, ua.y, ua.z, ua.w};
        float ubv[4] = {ub.x, ub.y, ub.z, ub.w};
#pragma unroll
        for (int kk = 0; kk < 4; kk++) {
            ulonglong2 w01 = __ldg(&W16[(k + kk) * 32 + wbase + 0]);  // pairs 0,1
            ulonglong2 w23 = __ldg(&W16[(k + kk) * 32 + wbase + 1]);  // pairs 2,3
            ulonglong2 w45 = __ldg(&W16[(k + kk) * 32 + wbase + 2]);  // pairs 4,5
            ulonglong2 w67 = __ldg(&W16[(k + kk) * 32 + wbase + 3]);  // pairs 6,7
            unsigned long long da = pack2dup(uav[kk]);
            unsigned long long db = pack2dup(ubv[kk]);
            fma2(acc[0][0], da, w01.x); fma2(acc[0][1], da, w01.y);
            fma2(acc[0][2], da, w23.x); fma2(acc[0][3], da, w23.y);
            fma2(acc[0][4], da, w45.x); fma2(acc[0][5], da, w45.y);
            fma2(acc[0][6], da, w67.x); fma2(acc[0][7], da, w67.y);
            fma2(acc[1][0], db, w01.x); fma2(acc[1][1], db, w01.y);
            fma2(acc[1][2], db, w23.x); fma2(acc[1][3], db, w23.y);
            fma2(acc[1][4], db, w45.x); fma2(acc[1][5], db, w45.y);
            fma2(acc[1][6], db, w67.x); fma2(acc[1][7], db, w67.y);
        }
    }

    // ---- Phase 3: epilogue (bias + relu) via smem transpose ----
    __syncthreads();   // all U reads done before overwriting Us
#pragma unroll
    for (int r = 0; r < 2; r++) {
        int rr = lane + r * 32;
#pragma unroll
        for (int p = 0; p < 8; p++) {
            int c = warp * 16 + p * 2;
            float2 bb = *reinterpret_cast<const float2*>(&b[c]);
            float lo, hi;
            unpack2(acc[r][p], lo, hi);
            float2 v = make_float2(fmaxf(lo + bb.x, 0.f), fmaxf(hi + bb.y, 0.f));
            *reinterpret_cast<float2*>(&Us[rr * UPAD + c]) = v;
        }
    }
    __syncthreads();
    for (int t = tid; t < GEMM_ROWS * (D / 4); t += 256) {
        int r  = t >> 5;
        int c4 = t & 31;
        int grow = row0 + r;
        if (grow < N_NODES)
            *reinterpret_cast<float4*>(&out[(size_t)grow * D + c4 * 4]) =
                *reinterpret_cast<const float4*>(&Us[r * UPAD + c4 * 4]);
    }
}

// ---------------------------------------------------------------------------
// Launch. Inputs: edge_list [800000,2] i32, x [50000,128] f32,
//                 W [128,128] f32, b [128] f32. Output f32 [50000,128].
// ---------------------------------------------------------------------------
extern "C" void kernel_launch(void* const* d_in, const int* in_sizes, int n_in,
                              void* d_out, int out_size) {
    const int2*  edges = (const int2*) d_in[0];
    const float* x     = (const float*)d_in[1];
    const float* Wm    = (const float*)d_in[2];
    const float* b     = (const float*)d_in[3];
    float* out = (float*)d_out;

    zero_kernel<<<ZB, 256>>>();
    prep2_kernel<<<DB + WB, 256>>>(edges, Wm);
    scale_scanA_kernel<<<SB + ZB, 256>>>(x);
    scanBC_kernel<<<ZB, 256>>>();
    fill_kernel<<<DB, 256>>>(edges);
    fused_kernel<<<(N_NODES + GEMM_ROWS - 1) / GEMM_ROWS, 256>>>(b, out);
}

// round 11
// speedup vs baseline: 1.2513x; 1.2513x over previous
#include <cuda_runtime.h>
#include <cuda_fp16.h>
#include <cstdint>

#define N_NODES 50000
#define N_EDGES 800000
#define D 128

// ---------------------------------------------------------------------------
// Device scratch
// ---------------------------------------------------------------------------
__device__ int     g_cin[N_NODES];        // deg_in  - 1 (src counts)
__device__ int     g_cnt[N_NODES];        // deg_out - 1 (dst counts)
__device__ int     g_rowptr[N_NODES + 1];
__device__ int     g_cursor[N_NODES];
__device__ int     g_col[N_EDGES];
__device__ float   g_sout[N_NODES];       // rsqrt(deg_out)
__device__ __half  g_xsh[N_NODES * D];    // fp16( x * rsqrt(deg_in) )
__device__ float2  g_Wk[(D / 2) * D];     // Wk[k2*128+j] = {W[j][2k2], W[j][2k2+1]}
__device__ int     g_bsum[256];           // per-block count sums (196 used)

// ---------------------------------------------------------------------------
// Packed f32x2 helpers
// ---------------------------------------------------------------------------
__device__ __forceinline__ void fma2(unsigned long long& d,
                                     unsigned long long a,
                                     unsigned long long b) {
    asm("fma.rn.f32x2 %0, %1, %2, %0;" : "+l"(d) : "l"(a), "l"(b));
}
__device__ __forceinline__ void unpack2(unsigned long long v, float& lo, float& hi) {
    asm("mov.b64 {%0, %1}, %2;" : "=f"(lo), "=f"(hi) : "l"(v));
}

#define ZB ((N_NODES + 255) / 256)        // 196
#define DB ((N_EDGES + 255) / 256)        // 3125
#define WB ((D * (D / 2) + 255) / 256)    // 32
#define SB ((N_NODES * (D / 4) + 255) / 256)  // 6250

// ---------------------------------------------------------------------------
// Kernel 1: zero degree counters
// ---------------------------------------------------------------------------
__global__ void zero_kernel() {
    int i = blockIdx.x * blockDim.x + threadIdx.x;
    if (i < N_NODES) { g_cin[i] = 0; g_cnt[i] = 0; }
}

// ---------------------------------------------------------------------------
// Kernel 2: degree counts + W k-pair pack (disjoint block ranges)
// ---------------------------------------------------------------------------
__global__ __launch_bounds__(256) void prep2_kernel(const int2* __restrict__ edges,
                                                    const float* __restrict__ Wm) {
    int bid = blockIdx.x;
    if (bid < DB) {
        int i = bid * 256 + threadIdx.x;
        if (i < N_EDGES) {
            int2 e = edges[i];
            atomicAdd(&g_cin[e.x], 1);
            atomicAdd(&g_cnt[e.y], 1);
        }
    } else {
        int i = (bid - DB) * 256 + threadIdx.x;
        if (i < (D / 2) * D) {
            int k2 = i >> 7;       // 0..63
            int j  = i & 127;      // col 0..127
            g_Wk[i] = make_float2(Wm[j * D + 2 * k2], Wm[j * D + 2 * k2 + 1]);
        }
    }
}

// ---------------------------------------------------------------------------
// Kernel 3: scale + scanA (disjoint block ranges)
// ---------------------------------------------------------------------------
__global__ __launch_bounds__(256) void scale_scanA_kernel(const float* __restrict__ x) {
    int bid = blockIdx.x;
    if (bid < SB) {
        int i = bid * 256 + threadIdx.x;         // float4 index
        if (i < N_NODES * (D / 4)) {
            int row = i >> 5;
            float s = rsqrtf((float)(g_cin[row] + 1));
            float4 v = reinterpret_cast<const float4*>(x)[i];
            __half2 h0 = __floats2half2_rn(v.x * s, v.y * s);
            __half2 h1 = __floats2half2_rn(v.z * s, v.w * s);
            *reinterpret_cast<__half2*>(&g_xsh[(size_t)i * 4])     = h0;
            *reinterpret_cast<__half2*>(&g_xsh[(size_t)i * 4 + 2]) = h1;
            if ((i & 31) == 0) g_sout[row] = rsqrtf((float)(g_cnt[row] + 1));
        }
    } else {
        __shared__ int sh[8];
        int blk = bid - SB;
        int i = blk * 256 + threadIdx.x;
        int v = (i < N_NODES) ? g_cnt[i] : 0;
        int lane = threadIdx.x & 31, warp = threadIdx.x >> 5;
#pragma unroll
        for (int o = 16; o > 0; o >>= 1) v += __shfl_down_sync(0xffffffffu, v, o);
        if (lane == 0) sh[warp] = v;
        __syncthreads();
        if (warp == 0) {
            int w = (lane < 8) ? sh[lane] : 0;
#pragma unroll
            for (int o = 4; o > 0; o >>= 1) w += __shfl_down_sync(0xffffffffu, w, o);
            if (lane == 0) g_bsum[blk] = w;
        }
    }
}

// ---------------------------------------------------------------------------
// Kernel 4: fused scanB+scanC
// ---------------------------------------------------------------------------
__global__ __launch_bounds__(256) void scanBC_kernel() {
    __shared__ int bs[256];
    __shared__ int sh[256];
    int t = threadIdx.x;

    int bv = (t < ZB) ? g_bsum[t] : 0;
    bs[t] = bv;
    __syncthreads();
    for (int off = 1; off < 256; off <<= 1) {
        int a = (t >= off) ? bs[t - off] : 0;
        __syncthreads();
        bs[t] += a;
        __syncthreads();
    }
    int boff  = (blockIdx.x > 0) ? bs[blockIdx.x - 1] : 0;
    int total = bs[ZB - 1];

    int i = blockIdx.x * 256 + t;
    int v = (i < N_NODES) ? g_cnt[i] : 0;
    sh[t] = v;
    __syncthreads();
    for (int off = 1; off < 256; off <<= 1) {
        int a = (t >= off) ? sh[t - off] : 0;
        __syncthreads();
        sh[t] += a;
        __syncthreads();
    }
    if (i < N_NODES) {
        int p = boff + sh[t] - v;
        g_rowptr[i] = p;
        g_cursor[i] = p;
    }
    if (blockIdx.x == 0 && t == 0) g_rowptr[N_NODES] = total;
}

// ---------------------------------------------------------------------------
// Kernel 5: fill CSR column array
// ---------------------------------------------------------------------------
__global__ void fill_kernel(const int2* __restrict__ edges) {
    int i = blockIdx.x * blockDim.x + threadIdx.x;
    if (i < N_EDGES) {
        int2 e = edges[i];
        int pos = atomicAdd(&g_cursor[e.y], 1);
        g_col[pos] = e.x;
    }
}

// ---------------------------------------------------------------------------
// Kernel 6: FUSED gather + GEMM. 32-row tile, warp-private rows.
//   Phase 1 (warp w): gather rows [4w, 4w+4) into smem (fp32), __syncwarp.
//   Phase 2: thread (w,l) computes its 4 rows x cols {l,l+32,l+64,l+96}
//     with k-pair FFMA2: acc += {u[2k2],u[2k2+1]} * {W[c][2k2],W[c][2k2+1]}.
//     U rows broadcast LDS.128 (warp-uniform addr); W k-pair packed LDG.64
//     (lane-contiguous, L1-resident). Zero packing MOVs.
// ---------------------------------------------------------------------------
#define GEMM_ROWS 32
__global__ __launch_bounds__(256, 3) void fused_kernel(
    const float* __restrict__ b, float* __restrict__ out) {
    __shared__ float Us[GEMM_ROWS * D];   // 16KB

    int tid  = threadIdx.x;
    int lane = tid & 31;
    int warp = tid >> 5;
    int row0 = blockIdx.x * GEMM_ROWS;
    int r0   = warp * 4;

    // ---- Phase 1: gather rows [4w, 4w+4) ----
    {
        const __half2* xs2 = reinterpret_cast<const __half2*>(g_xsh);
        int fo = lane * 2;                     // half2 index within row [0,64)
#pragma unroll
        for (int i = 0; i < 4; i++) {
            int node = row0 + r0 + i;
            float2 a0 = make_float2(0.f, 0.f);
            float2 a1 = make_float2(0.f, 0.f);
            if (node < N_NODES) {
                uint2 raw = *reinterpret_cast<const uint2*>(&xs2[(size_t)node * 64 + fo]);
                a0 = __half22float2(*reinterpret_cast<__half2*>(&raw.x));
                a1 = __half22float2(*reinterpret_cast<__half2*>(&raw.y));
                int s = g_rowptr[node];
                int e = g_rowptr[node + 1];
                int j = s;
                for (; j + 4 <= e; j += 4) {
                    int u0 = g_col[j + 0];
                    int u1 = g_col[j + 1];
                    int u2 = g_col[j + 2];
                    int u3 = g_col[j + 3];
                    uint2 q0 = *reinterpret_cast<const uint2*>(&xs2[(size_t)u0 * 64 + fo]);
                    uint2 q1 = *reinterpret_cast<const uint2*>(&xs2[(size_t)u1 * 64 + fo]);
                    uint2 q2 = *reinterpret_cast<const uint2*>(&xs2[(size_t)u2 * 64 + fo]);
                    uint2 q3 = *reinterpret_cast<const uint2*>(&xs2[(size_t)u3 * 64 + fo]);
                    float2 f;
                    f = __half22float2(*reinterpret_cast<__half2*>(&q0.x)); a0.x += f.x; a0.y += f.y;
                    f = __half22float2(*reinterpret_cast<__half2*>(&q0.y)); a1.x += f.x; a1.y += f.y;
                    f = __half22float2(*reinterpret_cast<__half2*>(&q1.x)); a0.x += f.x; a0.y += f.y;
                    f = __half22float2(*reinterpret_cast<__half2*>(&q1.y)); a1.x += f.x; a1.y += f.y;
                    f = __half22float2(*reinterpret_cast<__half2*>(&q2.x)); a0.x += f.x; a0.y += f.y;
                    f = __half22float2(*reinterpret_cast<__half2*>(&q2.y)); a1.x += f.x; a1.y += f.y;
                    f = __half22float2(*reinterpret_cast<__half2*>(&q3.x)); a0.x += f.x; a0.y += f.y;
                    f = __half22float2(*reinterpret_cast<__half2*>(&q3.y)); a1.x += f.x; a1.y += f.y;
                }
                for (; j < e; j++) {
                    int u = g_col[j];
                    uint2 q = *reinterpret_cast<const uint2*>(&xs2[(size_t)u * 64 + fo]);
                    float2 f;
                    f = __half22float2(*reinterpret_cast<__half2*>(&q.x)); a0.x += f.x; a0.y += f.y;
                    f = __half22float2(*reinterpret_cast<__half2*>(&q.y)); a1.x += f.x; a1.y += f.y;
                }
                float so = g_sout[node];
                a0.x *= so; a0.y *= so; a1.x *= so; a1.y *= so;
            }
            *reinterpret_cast<float4*>(&Us[(r0 + i) * D + lane * 4]) =
                make_float4(a0.x, a0.y, a1.x, a1.y);
        }
    }
    __syncwarp();

    // ---- Phase 2: GEMM (k-pair FFMA2) ----
    // acc[i][g]: row r0+i, col c = lane + 32g. lo = even-k partial, hi = odd-k.
    unsigned long long acc[4][4];
#pragma unroll
    for (int i = 0; i < 4; i++)
#pragma unroll
        for (int g = 0; g < 4; g++) acc[i][g] = 0ull;

    const float2* Wk = g_Wk;

#pragma unroll 8
    for (int k2 = 0; k2 < D / 2; k2 += 2) {     // 2 k-pairs (4 k) per iter
        // W: 8 coalesced LDG.64 (L1-resident)
        unsigned long long w0[4], w1[4];
#pragma unroll
        for (int g = 0; g < 4; g++) {
            w0[g] = *reinterpret_cast<const unsigned long long*>(&Wk[(k2 + 0) * D + lane + 32 * g]);
            w1[g] = *reinterpret_cast<const unsigned long long*>(&Wk[(k2 + 1) * D + lane + 32 * g]);
        }
#pragma unroll
        for (int i = 0; i < 4; i++) {
            // broadcast LDS.128: one row, 2 k-pairs -> 2 aligned ulls
            unsigned long long u01[2];
            *reinterpret_cast<float4*>(u01) =
                *reinterpret_cast<const float4*>(&Us[(r0 + i) * D + 2 * k2]);
            fma2(acc[i][0], u01[0], w0[0]);
            fma2(acc[i][1], u01[0], w0[1]);
            fma2(acc[i][2], u01[0], w0[2]);
            fma2(acc[i][3], u01[0], w0[3]);
            fma2(acc[i][0], u01[1], w1[0]);
            fma2(acc[i][1], u01[1], w1[1]);
            fma2(acc[i][2], u01[1], w1[2]);
            fma2(acc[i][3], u01[1], w1[3]);
        }
    }

    // ---- Epilogue: out[c] = relu(lo + hi + b[c]), coalesced 4B stores ----
    float bb[4];
#pragma unroll
    for (int g = 0; g < 4; g++) bb[g] = __ldg(&b[lane + 32 * g]);
#pragma unroll
    for (int i = 0; i < 4; i++) {
        int row = row0 + r0 + i;
        if (row < N_NODES) {
#pragma unroll
            for (int g = 0; g < 4; g++) {
                float lo, hi;
                unpack2(acc[i][g], lo, hi);
                out[(size_t)row * D + lane + 32 * g] = fmaxf(lo + hi + bb[g], 0.f);
            }
        }
    }
}

// ---------------------------------------------------------------------------
// Launch. Inputs: edge_list [800000,2] i32, x [50000,128] f32,
//                 W [128,128] f32, b [128] f32. Output f32 [50000,128].
// ---------------------------------------------------------------------------
extern "C" void kernel_launch(void* const* d_in, const int* in_sizes, int n_in,
                              void* d_out, int out_size) {
    const int2*  edges = (const int2*) d_in[0];
    const float* x     = (const float*)d_in[1];
    const float* Wm    = (const float*)d_in[2];
    const float* b     = (const float*)d_in[3];
    float* out = (float*)d_out;

    zero_kernel<<<ZB, 256>>>();
    prep2_kernel<<<DB + WB, 256>>>(edges, Wm);
    scale_scanA_kernel<<<SB + ZB, 256>>>(x);
    scanBC_kernel<<<ZB, 256>>>();
    fill_kernel<<<DB, 256>>>(edges);
    fused_kernel<<<(N_NODES + GEMM_ROWS - 1) / GEMM_ROWS, 256>>>(b, out);
}